// round 2
// baseline (speedup 1.0000x reference)
#include <cuda_runtime.h>
#include <cuda_bf16.h>
#include <cstdint>

// Problem dims (fixed by the dataset)
#define BQ   2048        // batch rows
#define DD   128         // query dim
#define MM   256         // projection dim
#define NK   32768       // number of keys
#define KSPLIT 512       // hi|lo concatenated K
#define EST_CONST 0.0048957583f   // sqrt(pi/2)/256

// ---------------- device scratch (static; no runtime alloc) ----------------
__device__ __nv_bfloat16 g_A[BQ * KSPLIT];     // [2048][512] hi|lo of projected query (2 MB)
__device__ __nv_bfloat16 g_B[NK * MM];         // keys in bf16 [32768][256] (16 MB)
__device__ float g_scl[NK];                    // EST_CONST * key_norms
__device__ float g_pmax[16 * 256 * 128];       // per (rowblock, colblock, row) tile max
__device__ float g_psum[16 * 256 * 128];       // per-tile sum of exp(x - tilemax)
__device__ float g_rowm[BQ];
__device__ float g_rowinv[BQ];

// ---------------- kernel 0: convert keys to bf16, build scales -------------
__global__ void convert_keys_kernel(const float* __restrict__ keys,
                                    const float* __restrict__ norms) {
    int idx = blockIdx.x * blockDim.x + threadIdx.x;   // grid covers NK*MM exactly
    g_B[idx] = __float2bfloat16(keys[idx]);
    if (idx < NK) g_scl[idx] = EST_CONST * norms[idx];
}

// ---------------- kernel 1: project query + bf16 hi/lo split ----------------
// grid = 128 blocks, each handles 16 query rows; 256 threads (one per m)
__global__ __launch_bounds__(256) void proj_kernel(const float* __restrict__ q,
                                                   const float* __restrict__ S) {
    __shared__ float qs[16][128];
    int blk = blockIdx.x;
    int tid = threadIdx.x;
#pragma unroll
    for (int p = 0; p < 8; p++) {
        int e = p * 256 + tid;                 // 2048 elements
        qs[e >> 7][e & 127] = q[blk * 16 * DD + e];
    }
    __syncthreads();
    int m = tid;
    float acc[16];
#pragma unroll
    for (int i = 0; i < 16; i++) acc[i] = 0.f;
    for (int d = 0; d < DD; d++) {
        float sv = S[m * DD + d];
#pragma unroll
        for (int i = 0; i < 16; i++) acc[i] += qs[i][d] * sv;
    }
#pragma unroll
    for (int i = 0; i < 16; i++) {
        int b = blk * 16 + i;
        float v = acc[i];
        __nv_bfloat16 hi = __float2bfloat16(v);
        float lo = v - __bfloat162float(hi);
        g_A[b * KSPLIT + m]       = hi;
        g_A[b * KSPLIT + MM + m]  = __float2bfloat16(lo);
    }
}

// ---------------- kernel 2: big GEMM + scale + partial softmax stats --------
// CTA tile: 128 (rows) x 128 (keys), K loop over 512 in steps of 64.
// 8 warps as 4x2; warp tile 32x64 via m16n8k16 bf16 mma.
__global__ __launch_bounds__(256, 2) void gemm_kernel(float* __restrict__ out) {
    __shared__ __nv_bfloat16 As[128][72];
    __shared__ __nv_bfloat16 Bs[128][72];
    __shared__ float sclS[128];
    __shared__ float redm[128][2];
    __shared__ float reds[128][2];

    int tid  = threadIdx.x;
    int warp = tid >> 5, lane = tid & 31;
    int wm = warp >> 1, wn = warp & 1;
    int rb = blockIdx.y, cb = blockIdx.x;
    int row0 = rb * 128;
    int col0 = cb * 128;

    if (tid < 128) sclS[tid] = g_scl[col0 + tid];

    float acc[2][8][4];
#pragma unroll
    for (int i = 0; i < 2; i++)
#pragma unroll
        for (int j = 0; j < 8; j++)
#pragma unroll
            for (int k = 0; k < 4; k++) acc[i][j][k] = 0.f;

    int lrow  = (lane & 7) + (lane & 8);     // ldmatrix row within 16-row group
    int lcolo = (lane >> 4) << 3;            // 0 or 8 (k offset)

    for (int k0 = 0; k0 < KSPLIT; k0 += 64) {
        int kB = k0 & (MM - 1);              // keys wrap: hi and lo share B
        __syncthreads();
#pragma unroll
        for (int p = 0; p < 4; p++) {
            int r = (tid >> 3) + p * 32;
            int c = (tid & 7) * 8;
            *(uint4*)&As[r][c] = *(const uint4*)&g_A[(size_t)(row0 + r) * KSPLIT + k0 + c];
            *(uint4*)&Bs[r][c] = *(const uint4*)&g_B[(size_t)(col0 + r) * MM + kB + c];
        }
        __syncthreads();
#pragma unroll
        for (int kk = 0; kk < 64; kk += 16) {
            uint32_t a[2][4];
#pragma unroll
            for (int mf = 0; mf < 2; mf++) {
                uint32_t addr = (uint32_t)__cvta_generic_to_shared(
                    &As[wm * 32 + mf * 16 + lrow][kk + lcolo]);
                asm volatile("ldmatrix.sync.aligned.m8n8.x4.shared.b16 {%0,%1,%2,%3}, [%4];"
                             : "=r"(a[mf][0]), "=r"(a[mf][1]), "=r"(a[mf][2]), "=r"(a[mf][3])
                             : "r"(addr));
            }
            uint32_t b[8][2];
#pragma unroll
            for (int nq = 0; nq < 4; nq++) {
                uint32_t r0, r1, r2, r3;
                uint32_t addr = (uint32_t)__cvta_generic_to_shared(
                    &Bs[wn * 64 + nq * 16 + lrow][kk + lcolo]);
                asm volatile("ldmatrix.sync.aligned.m8n8.x4.shared.b16 {%0,%1,%2,%3}, [%4];"
                             : "=r"(r0), "=r"(r1), "=r"(r2), "=r"(r3)
                             : "r"(addr));
                b[nq * 2][0] = r0; b[nq * 2][1] = r2;
                b[nq * 2 + 1][0] = r1; b[nq * 2 + 1][1] = r3;
            }
#pragma unroll
            for (int mf = 0; mf < 2; mf++)
#pragma unroll
                for (int nf = 0; nf < 8; nf++)
                    asm volatile(
                        "mma.sync.aligned.m16n8k16.row.col.f32.bf16.bf16.f32 "
                        "{%0,%1,%2,%3}, {%4,%5,%6,%7}, {%8,%9}, {%0,%1,%2,%3};"
                        : "+f"(acc[mf][nf][0]), "+f"(acc[mf][nf][1]),
                          "+f"(acc[mf][nf][2]), "+f"(acc[mf][nf][3])
                        : "r"(a[mf][0]), "r"(a[mf][1]), "r"(a[mf][2]), "r"(a[mf][3]),
                          "r"(b[nf][0]), "r"(b[nf][1]));
        }
    }

    // ---------------- epilogue: scale, store, per-row (max, sumexp) ----------
    int q  = lane & 3;
    int rq = lane >> 2;

    float rmax[2][2];
#pragma unroll
    for (int mf = 0; mf < 2; mf++)
#pragma unroll
        for (int h = 0; h < 2; h++) rmax[mf][h] = -1e30f;

#pragma unroll
    for (int mf = 0; mf < 2; mf++)
#pragma unroll
        for (int nf = 0; nf < 8; nf++) {
            int c = wn * 64 + nf * 8 + q * 2;
            float s0 = sclS[c], s1 = sclS[c + 1];
#pragma unroll
            for (int h = 0; h < 2; h++) {
                float v0 = acc[mf][nf][h * 2 + 0] * s0;
                float v1 = acc[mf][nf][h * 2 + 1] * s1;
                acc[mf][nf][h * 2 + 0] = v0;
                acc[mf][nf][h * 2 + 1] = v1;
                rmax[mf][h] = fmaxf(rmax[mf][h], fmaxf(v0, v1));
                int grow = row0 + wm * 32 + mf * 16 + h * 8 + rq;
                float2 w = make_float2(v0, v1);
                *(float2*)&out[(size_t)grow * NK + col0 + c] = w;
            }
        }

#pragma unroll
    for (int mf = 0; mf < 2; mf++)
#pragma unroll
        for (int h = 0; h < 2; h++) {
            float m = rmax[mf][h];
            m = fmaxf(m, __shfl_xor_sync(0xffffffff, m, 1));
            m = fmaxf(m, __shfl_xor_sync(0xffffffff, m, 2));
            if (q == 0) redm[wm * 32 + mf * 16 + h * 8 + rq][wn] = m;
        }
    __syncthreads();

#pragma unroll
    for (int mf = 0; mf < 2; mf++)
#pragma unroll
        for (int h = 0; h < 2; h++) {
            int r = wm * 32 + mf * 16 + h * 8 + rq;
            float m = fmaxf(redm[r][0], redm[r][1]);   // full 128-col tile max
            float s = 0.f;
#pragma unroll
            for (int nf = 0; nf < 8; nf++) {
                s += __expf(acc[mf][nf][h * 2 + 0] - m);
                s += __expf(acc[mf][nf][h * 2 + 1] - m);
            }
            s += __shfl_xor_sync(0xffffffff, s, 1);
            s += __shfl_xor_sync(0xffffffff, s, 2);
            if (q == 0) reds[r][wn] = s;
        }
    __syncthreads();

    if (tid < 128) {
        int r = tid;
        float m = fmaxf(redm[r][0], redm[r][1]);
        float s = reds[r][0] + reds[r][1];
        int idx = (rb * 256 + cb) * 128 + r;
        g_pmax[idx] = m;
        g_psum[idx] = s;
    }
}

// ---------------- kernel 3: merge partial softmax stats ----------------------
__global__ void reduce_kernel() {
    int b = blockIdx.x * blockDim.x + threadIdx.x;
    if (b >= BQ) return;
    int rb = b >> 7, r = b & 127;
    const float* pm = g_pmax + rb * 256 * 128 + r;
    const float* ps = g_psum + rb * 256 * 128 + r;
    float m = -1e30f;
    for (int cb = 0; cb < 256; cb++) m = fmaxf(m, pm[cb * 128]);
    float s = 0.f;
    for (int cb = 0; cb < 256; cb++) s += ps[cb * 128] * __expf(pm[cb * 128] - m);
    g_rowm[b] = m;
    g_rowinv[b] = 1.f / s;
}

// ---------------- kernel 4: in-place finalize out = exp(x-m)*inv -------------
__global__ __launch_bounds__(256) void finalize_kernel(float* __restrict__ out) {
    size_t i = (size_t)blockIdx.x * blockDim.x + threadIdx.x;   // over float4s
    float4* o4 = (float4*)out;
    int b = (int)(i >> 13);                  // 8192 float4 per row
    float m = g_rowm[b], inv = g_rowinv[b];
    float4 v = o4[i];
    v.x = __expf(v.x - m) * inv;
    v.y = __expf(v.y - m) * inv;
    v.z = __expf(v.z - m) * inv;
    v.w = __expf(v.w - m) * inv;
    o4[i] = v;
}

// ---------------- launcher ---------------------------------------------------
extern "C" void kernel_launch(void* const* d_in, const int* in_sizes, int n_in,
                              void* d_out, int out_size) {
    const float* query  = (const float*)d_in[0];   // [2048,128]
    const float* keys   = (const float*)d_in[1];   // [32768,256]
    const float* norms  = (const float*)d_in[2];   // [32768]
    const float* sketch = (const float*)d_in[3];   // [256,128]
    float* out = (float*)d_out;

    convert_keys_kernel<<<NK * MM / 256, 256>>>(keys, norms);
    proj_kernel<<<BQ / 16, 256>>>(query, sketch);
    dim3 ggrid(NK / 128, BQ / 128);
    gemm_kernel<<<ggrid, 256>>>(out);
    reduce_kernel<<<BQ / 256, 256>>>();
    finalize_kernel<<<(size_t)BQ * NK / 4 / 256, 256>>>(out);
}

// round 4
// speedup vs baseline: 1.1042x; 1.1042x over previous
#include <cuda_runtime.h>
#include <cuda_bf16.h>
#include <cstdint>

// Problem dims (fixed by the dataset)
#define BQ   2048
#define DD   128
#define MM   256
#define NK   32768
#define KSPLIT 512
#define EST_CONST 0.0048957583f   // sqrt(pi/2)/256

#define TILE_N 128
#define NCB    (NK / TILE_N)      // 256 column blocks

// ---------------- device scratch ----------------
__device__ __nv_bfloat16 g_A[BQ * KSPLIT];     // hi|lo projected query (2 MB)
__device__ __nv_bfloat16 g_B[NK * MM];         // keys bf16 (16 MB)
__device__ float g_scl[NK];
__device__ float g_pmax[BQ * NCB];             // [row][cb]
__device__ float g_psum[BQ * NCB];
__device__ float g_rowm[BQ];
__device__ float g_rowinv[BQ];

__device__ __forceinline__ uint32_t smem_u32(const void* p) {
    uint32_t a;
    asm("{ .reg .u64 t; cvta.to.shared.u64 t, %1; cvt.u32.u64 %0, t; }" : "=r"(a) : "l"(p));
    return a;
}
#define CP16(dst, src) asm volatile("cp.async.cg.shared.global [%0], [%1], 16;" :: "r"(dst), "l"(src))
#define CP_COMMIT()    asm volatile("cp.async.commit_group;" ::: "memory")

// ---------------- kernel 0: convert keys + scales (vectorized) --------------
__global__ __launch_bounds__(256) void convert_keys_kernel(const float* __restrict__ keys,
                                                           const float* __restrict__ norms) {
    int i = blockIdx.x * blockDim.x + threadIdx.x;        // over float4, NK*MM/4
    float4 v = ((const float4*)keys)[i];
    __nv_bfloat162* o = (__nv_bfloat162*)g_B;
    o[i * 2]     = __nv_bfloat162(__float2bfloat16(v.x), __float2bfloat16(v.y));
    o[i * 2 + 1] = __nv_bfloat162(__float2bfloat16(v.z), __float2bfloat16(v.w));
    if (i < NK) g_scl[i] = EST_CONST * norms[i];
}

// ---------------- kernel 1: project query + hi/lo split ----------------------
__global__ __launch_bounds__(256) void proj_kernel(const float* __restrict__ q,
                                                   const float* __restrict__ S) {
    __shared__ float qs[16][128];
    int blk = blockIdx.x, tid = threadIdx.x;
#pragma unroll
    for (int p = 0; p < 8; p++) {
        int e = p * 256 + tid;
        qs[e >> 7][e & 127] = q[blk * 16 * DD + e];
    }
    __syncthreads();
    int m = tid;
    float acc[16];
#pragma unroll
    for (int i = 0; i < 16; i++) acc[i] = 0.f;
    for (int d = 0; d < DD; d++) {
        float sv = S[m * DD + d];
#pragma unroll
        for (int i = 0; i < 16; i++) acc[i] += qs[i][d] * sv;
    }
#pragma unroll
    for (int i = 0; i < 16; i++) {
        int b = blk * 16 + i;
        float v = acc[i];
        __nv_bfloat16 hi = __float2bfloat16(v);
        float lo = v - __bfloat162float(hi);
        g_A[b * KSPLIT + m]      = hi;
        g_A[b * KSPLIT + MM + m] = __float2bfloat16(lo);
    }
}

// ---------------- kernel 2: pipelined mma.sync GEMM + softmax partials -------
// CTA 128x128, K=512 in 8 chunks of 64, cp.async 2-stage double buffer.
// smem per stage: A[128][72] + B[128][72] bf16 = 36864 B. 2 stages = 73728 B.
// Epilogue stages the fp32 tile in the same smem (67584 B needed, 132-f stride).
#define ROWSTR   72                    // bf16 elems per smem row (144 B)
#define ABYTES   (128 * ROWSTR * 2)    // 18432
#define STAGE_BYTES (2 * ABYTES)       // 36864
#define SMEM_BYTES  (2 * STAGE_BYTES)  // 73728

extern __shared__ char dsm[];

__device__ __forceinline__ void load_chunk(uint32_t sb, int stage, int k0,
                                           int row0, int col0, int tid) {
    uint32_t base = sb + stage * STAGE_BYTES;
    int kB = k0 & (MM - 1);
#pragma unroll
    for (int i = 0; i < 4; i++) {
        int u = tid + i * 256;
        int r = u >> 3, c = (u & 7) * 8;              // c in elems
        uint32_t off = (uint32_t)(r * (ROWSTR * 2) + c * 2);
        CP16(base + off, &g_A[(size_t)(row0 + r) * KSPLIT + k0 + c]);
        CP16(base + ABYTES + off, &g_B[(size_t)(col0 + r) * MM + kB + c]);
    }
}

__global__ __launch_bounds__(256, 2) void gemm_kernel(float* __restrict__ out) {
    uint32_t sb = smem_u32(dsm);
    int tid  = threadIdx.x;
    int warp = tid >> 5, lane = tid & 31;
    int wm = warp >> 1, wn = warp & 1;
    int rb = blockIdx.y, cb = blockIdx.x;
    int row0 = rb * 128, col0 = cb * TILE_N;

    __shared__ float sclS[TILE_N];
    __shared__ float redm[128][2];
    __shared__ float reds[128][2];

    if (tid < TILE_N) sclS[tid] = g_scl[col0 + tid];

    float acc[2][8][4];
#pragma unroll
    for (int i = 0; i < 2; i++)
#pragma unroll
        for (int j = 0; j < 8; j++)
#pragma unroll
            for (int k = 0; k < 4; k++) acc[i][j][k] = 0.f;

    int lrow  = (lane & 7) + (lane & 8);
    int lcolo = (lane >> 4) << 3;

    load_chunk(sb, 0, 0, row0, col0, tid);
    CP_COMMIT();

#pragma unroll 1
    for (int c = 0; c < 8; c++) {
        if (c < 7) {
            load_chunk(sb, (c + 1) & 1, (c + 1) * 64, row0, col0, tid);
            CP_COMMIT();
            asm volatile("cp.async.wait_group 1;" ::: "memory");
        } else {
            asm volatile("cp.async.wait_group 0;" ::: "memory");
        }
        __syncthreads();
        uint32_t abase = sb + (c & 1) * STAGE_BYTES;
        uint32_t bbase = abase + ABYTES;
#pragma unroll
        for (int kk = 0; kk < 64; kk += 16) {
            uint32_t a[2][4];
#pragma unroll
            for (int mf = 0; mf < 2; mf++) {
                uint32_t addr = abase + (uint32_t)((wm * 32 + mf * 16 + lrow) * (ROWSTR * 2)
                                                   + (kk + lcolo) * 2);
                asm volatile("ldmatrix.sync.aligned.m8n8.x4.shared.b16 {%0,%1,%2,%3}, [%4];"
                             : "=r"(a[mf][0]), "=r"(a[mf][1]), "=r"(a[mf][2]), "=r"(a[mf][3])
                             : "r"(addr));
            }
            uint32_t b[8][2];
#pragma unroll
            for (int nq = 0; nq < 4; nq++) {
                uint32_t r0, r1, r2, r3;
                uint32_t addr = bbase + (uint32_t)((wn * 64 + nq * 16 + lrow) * (ROWSTR * 2)
                                                   + (kk + lcolo) * 2);
                asm volatile("ldmatrix.sync.aligned.m8n8.x4.shared.b16 {%0,%1,%2,%3}, [%4];"
                             : "=r"(r0), "=r"(r1), "=r"(r2), "=r"(r3)
                             : "r"(addr));
                b[nq * 2][0] = r0;     b[nq * 2][1] = r2;
                b[nq * 2 + 1][0] = r1; b[nq * 2 + 1][1] = r3;
            }
#pragma unroll
            for (int mf = 0; mf < 2; mf++)
#pragma unroll
                for (int nf = 0; nf < 8; nf++)
                    asm volatile(
                        "mma.sync.aligned.m16n8k16.row.col.f32.bf16.bf16.f32 "
                        "{%0,%1,%2,%3}, {%4,%5,%6,%7}, {%8,%9}, {%0,%1,%2,%3};"
                        : "+f"(acc[mf][nf][0]), "+f"(acc[mf][nf][1]),
                          "+f"(acc[mf][nf][2]), "+f"(acc[mf][nf][3])
                        : "r"(a[mf][0]), "r"(a[mf][1]), "r"(a[mf][2]), "r"(a[mf][3]),
                          "r"(b[nf][0]), "r"(b[nf][1]));
        }
        __syncthreads();   // protect buffer (c-1)&1 before next load overwrites
    }

    // ---------------- epilogue: scale + stats + staged coalesced store -------
    float* stage = (float*)dsm;            // [128][132] fp32, aliases cp buffers
    int q  = lane & 3;
    int rq = lane >> 2;

    float rmax[2][2];
#pragma unroll
    for (int mf = 0; mf < 2; mf++)
#pragma unroll
        for (int h = 0; h < 2; h++) rmax[mf][h] = -1e30f;

#pragma unroll
    for (int mf = 0; mf < 2; mf++)
#pragma unroll
        for (int nf = 0; nf < 8; nf++) {
            int c = wn * 64 + nf * 8 + q * 2;
            float s0 = sclS[c], s1 = sclS[c + 1];
#pragma unroll
            for (int h = 0; h < 2; h++) {
                float v0 = acc[mf][nf][h * 2 + 0] * s0;
                float v1 = acc[mf][nf][h * 2 + 1] * s1;
                acc[mf][nf][h * 2 + 0] = v0;
                acc[mf][nf][h * 2 + 1] = v1;
                rmax[mf][h] = fmaxf(rmax[mf][h], fmaxf(v0, v1));
                int r = wm * 32 + mf * 16 + h * 8 + rq;
                stage[r * 132 + c]     = v0;
                stage[r * 132 + c + 1] = v1;
            }
        }

    // per-row tile max across the 2 column-half warps
#pragma unroll
    for (int mf = 0; mf < 2; mf++)
#pragma unroll
        for (int h = 0; h < 2; h++) {
            float m = rmax[mf][h];
            m = fmaxf(m, __shfl_xor_sync(0xffffffff, m, 1));
            m = fmaxf(m, __shfl_xor_sync(0xffffffff, m, 2));
            if (q == 0) redm[wm * 32 + mf * 16 + h * 8 + rq][wn] = m;
        }
    __syncthreads();

#pragma unroll
    for (int mf = 0; mf < 2; mf++)
#pragma unroll
        for (int h = 0; h < 2; h++) {
            int r = wm * 32 + mf * 16 + h * 8 + rq;
            float m = fmaxf(redm[r][0], redm[r][1]);
            float s = 0.f;
#pragma unroll
            for (int nf = 0; nf < 8; nf++) {
                s += __expf(acc[mf][nf][h * 2 + 0] - m);
                s += __expf(acc[mf][nf][h * 2 + 1] - m);
            }
            s += __shfl_xor_sync(0xffffffff, s, 1);
            s += __shfl_xor_sync(0xffffffff, s, 2);
            if (q == 0) reds[r][wn] = s;
        }
    __syncthreads();

    if (tid < 128) {
        float m = fmaxf(redm[tid][0], redm[tid][1]);
        float s = reds[tid][0] + reds[tid][1];
        g_pmax[(size_t)(row0 + tid) * NCB + cb] = m;
        g_psum[(size_t)(row0 + tid) * NCB + cb] = s;
    }

    // coalesced tile store: warp w covers rows w*4+(lane>>3) (+32 per rr pass),
    // 8 lanes * float4 = 128 B contiguous per row per k step
#pragma unroll
    for (int rr = 0; rr < 4; rr++) {
        int r = rr * 32 + warp * 4 + (lane >> 3);
#pragma unroll
        for (int k = 0; k < 4; k++) {
            int col = (lane & 7) * 4 + k * 32;
            float4 v = *(const float4*)&stage[r * 132 + col];
            *(float4*)&out[(size_t)(row0 + r) * NK + col0 + col] = v;
        }
    }
}

// ---------------- kernel 3: merge partials (one block per row) ---------------
__global__ __launch_bounds__(256) void reduce_kernel() {
    int b = blockIdx.x, t = threadIdx.x;
    int wid = t >> 5, lane = t & 31;
    __shared__ float sm[8], ss[8];
    float pm = g_pmax[(size_t)b * NCB + t];
    float ps = g_psum[(size_t)b * NCB + t];
    float M = pm;
#pragma unroll
    for (int o = 16; o; o >>= 1) M = fmaxf(M, __shfl_xor_sync(0xffffffff, M, o));
    if (lane == 0) sm[wid] = M;
    __syncthreads();
    float M0 = sm[lane & 7];
#pragma unroll
    for (int o = 4; o; o >>= 1) M0 = fmaxf(M0, __shfl_xor_sync(0xffffffff, M0, o));
    M = __shfl_sync(0xffffffff, M0, 0);
    float s = ps * __expf(pm - M);
#pragma unroll
    for (int o = 16; o; o >>= 1) s += __shfl_xor_sync(0xffffffff, s, o);
    if (lane == 0) ss[wid] = s;
    __syncthreads();
    if (t == 0) {
        float S = ss[0] + ss[1] + ss[2] + ss[3] + ss[4] + ss[5] + ss[6] + ss[7];
        g_rowm[b] = M;
        g_rowinv[b] = 1.f / S;
    }
}

// ---------------- kernel 4: finalize out = exp(x-m)*inv ----------------------
__global__ __launch_bounds__(256) void finalize_kernel(float* __restrict__ out) {
    size_t i = (size_t)blockIdx.x * blockDim.x + threadIdx.x;
    float4* o4 = (float4*)out;
    int b = (int)(i >> 13);                 // 8192 float4 per row
    float m = g_rowm[b], inv = g_rowinv[b];
    float4 v = o4[i];
    v.x = __expf(v.x - m) * inv;
    v.y = __expf(v.y - m) * inv;
    v.z = __expf(v.z - m) * inv;
    v.w = __expf(v.w - m) * inv;
    o4[i] = v;
}

// ---------------- launcher ---------------------------------------------------
extern "C" void kernel_launch(void* const* d_in, const int* in_sizes, int n_in,
                              void* d_out, int out_size) {
    const float* query  = (const float*)d_in[0];
    const float* keys   = (const float*)d_in[1];
    const float* norms  = (const float*)d_in[2];
    const float* sketch = (const float*)d_in[3];
    float* out = (float*)d_out;

    cudaFuncSetAttribute(gemm_kernel, cudaFuncAttributeMaxDynamicSharedMemorySize, SMEM_BYTES);

    convert_keys_kernel<<<NK * MM / 1024, 256>>>(keys, norms);
    proj_kernel<<<BQ / 16, 256>>>(query, sketch);
    dim3 ggrid(NCB, BQ / 128);
    gemm_kernel<<<ggrid, 256, SMEM_BYTES>>>(out);
    reduce_kernel<<<BQ, 256>>>();
    finalize_kernel<<<(size_t)BQ * NK / 4 / 256, 256>>>(out);
}